// round 1
// baseline (speedup 1.0000x reference)
#include <cuda_runtime.h>
#include <cuda_bf16.h>
#include <cstdint>

#define EXP    8
#define DIN    2048
#define DOUT   2048
#define NTOK   4096
#define KROUTE 2
#define MTOT   (NTOK * KROUTE)

#define TM 128
#define TN 128
#define TK 32
#define KB (DIN / TK)
#define LDSS 40                   // padded smem row stride in bf16 elems (80B -> conflict-free LDSM)
#define TILEB (TM * LDSS * 2)     // 10240 bytes per tile buffer

// ---- scratch (device globals; no runtime allocation allowed) ----
__device__ __nv_bfloat16 g_w_hi[(size_t)EXP * DOUT * DIN];
__device__ __nv_bfloat16 g_w_lo[(size_t)EXP * DOUT * DIN];
__device__ __nv_bfloat16 g_x_hi[(size_t)NTOK * DIN];
__device__ __nv_bfloat16 g_x_lo[(size_t)NTOK * DIN];

// ---------------- PTX helpers ----------------
__device__ __forceinline__ void cpa16(uint32_t dst, const void* src, int bytes) {
    asm volatile("cp.async.cg.shared.global [%0], [%1], 16, %2;\n"
                 :: "r"(dst), "l"(src), "r"(bytes));
}
__device__ __forceinline__ void cp_commit() { asm volatile("cp.async.commit_group;\n"); }
__device__ __forceinline__ void cp_wait0()  { asm volatile("cp.async.wait_group 0;\n"); }

__device__ __forceinline__ void ldm4(uint32_t* r, uint32_t a) {
    asm volatile("ldmatrix.sync.aligned.m8n8.x4.shared.b16 {%0,%1,%2,%3}, [%4];\n"
                 : "=r"(r[0]), "=r"(r[1]), "=r"(r[2]), "=r"(r[3]) : "r"(a));
}
__device__ __forceinline__ void mma16816(float* c, const uint32_t* a, uint32_t b0, uint32_t b1) {
    asm volatile("mma.sync.aligned.m16n8k16.row.col.f32.bf16.bf16.f32 "
                 "{%0,%1,%2,%3}, {%4,%5,%6,%7}, {%8,%9}, {%0,%1,%2,%3};\n"
                 : "+f"(c[0]), "+f"(c[1]), "+f"(c[2]), "+f"(c[3])
                 : "r"(a[0]), "r"(a[1]), "r"(a[2]), "r"(a[3]), "r"(b0), "r"(b1));
}
__device__ __forceinline__ void red2(float* p, float v0, float v1) {
    asm volatile("red.global.add.v2.f32 [%0], {%1,%2};\n" :: "l"(p), "f"(v0), "f"(v1) : "memory");
}

// ---------------- prep: W_eff = W + 2*B@A, split to bf16 hi/lo ----------------
__global__ void __launch_bounds__(256) prep_weff_kernel(
    const float* __restrict__ weight, const float* __restrict__ lA,
    const float* __restrict__ lB)
{
    __shared__ float Bs[64][16];
    __shared__ float As[16][64];
    const int b = blockIdx.x;
    const int e = b >> 10;            // 32*32 tiles per expert
    const int jt = (b >> 5) & 31;
    const int dt = b & 31;
    const int j0 = jt * 64, d0 = dt * 64;
    const int t = threadIdx.x;
    {
        int jj = t >> 2, q = t & 3;
        float4 v = *reinterpret_cast<const float4*>(lB + ((size_t)e * DOUT + j0 + jj) * 16 + q * 4);
        Bs[jj][q * 4 + 0] = v.x; Bs[jj][q * 4 + 1] = v.y;
        Bs[jj][q * 4 + 2] = v.z; Bs[jj][q * 4 + 3] = v.w;
    }
    {
        int r = t >> 4, dd = (t & 15) * 4;
        float4 v = *reinterpret_cast<const float4*>(lA + ((size_t)e * 16 + r) * DIN + d0 + dd);
        As[r][dd + 0] = v.x; As[r][dd + 1] = v.y; As[r][dd + 2] = v.z; As[r][dd + 3] = v.w;
    }
    __syncthreads();
    const int tj = t >> 4, td = t & 15;
    #pragma unroll
    for (int a = 0; a < 4; a++) {
        int jj = tj * 4 + a;
        size_t base = ((size_t)e * DOUT + j0 + jj) * DIN + d0 + td * 4;
        float4 w = *reinterpret_cast<const float4*>(weight + base);
        float dw0 = 0.f, dw1 = 0.f, dw2 = 0.f, dw3 = 0.f;
        #pragma unroll
        for (int r = 0; r < 16; r++) {
            float bb = Bs[jj][r];
            dw0 += bb * As[r][td * 4 + 0];
            dw1 += bb * As[r][td * 4 + 1];
            dw2 += bb * As[r][td * 4 + 2];
            dw3 += bb * As[r][td * 4 + 3];
        }
        float v0 = w.x + 2.0f * dw0;
        float v1 = w.y + 2.0f * dw1;
        float v2 = w.z + 2.0f * dw2;
        float v3 = w.w + 2.0f * dw3;
        __nv_bfloat16 h0 = __float2bfloat16(v0), h1 = __float2bfloat16(v1);
        __nv_bfloat16 h2 = __float2bfloat16(v2), h3 = __float2bfloat16(v3);
        reinterpret_cast<__nv_bfloat162*>(g_w_hi + base)[0] = __halves2bfloat162(h0, h1);
        reinterpret_cast<__nv_bfloat162*>(g_w_hi + base)[1] = __halves2bfloat162(h2, h3);
        __nv_bfloat16 L0 = __float2bfloat16(v0 - __bfloat162float(h0));
        __nv_bfloat16 L1 = __float2bfloat16(v1 - __bfloat162float(h1));
        __nv_bfloat16 L2 = __float2bfloat16(v2 - __bfloat162float(h2));
        __nv_bfloat16 L3 = __float2bfloat16(v3 - __bfloat162float(h3));
        reinterpret_cast<__nv_bfloat162*>(g_w_lo + base)[0] = __halves2bfloat162(L0, L1);
        reinterpret_cast<__nv_bfloat162*>(g_w_lo + base)[1] = __halves2bfloat162(L2, L3);
    }
}

// ---------------- prep: split inputs to bf16 hi/lo ----------------
__global__ void __launch_bounds__(256) prep_x_kernel(const float* __restrict__ x) {
    size_t i = ((size_t)blockIdx.x * 256 + threadIdx.x) * 4;
    float4 v = *reinterpret_cast<const float4*>(x + i);
    __nv_bfloat16 h0 = __float2bfloat16(v.x);
    __nv_bfloat16 h1 = __float2bfloat16(v.y);
    __nv_bfloat16 h2 = __float2bfloat16(v.z);
    __nv_bfloat16 h3 = __float2bfloat16(v.w);
    reinterpret_cast<__nv_bfloat162*>(g_x_hi + i)[0] = __halves2bfloat162(h0, h1);
    reinterpret_cast<__nv_bfloat162*>(g_x_hi + i)[1] = __halves2bfloat162(h2, h3);
    __nv_bfloat16 l0 = __float2bfloat16(v.x - __bfloat162float(h0));
    __nv_bfloat16 l1 = __float2bfloat16(v.y - __bfloat162float(h1));
    __nv_bfloat16 l2 = __float2bfloat16(v.z - __bfloat162float(h2));
    __nv_bfloat16 l3 = __float2bfloat16(v.w - __bfloat162float(h3));
    reinterpret_cast<__nv_bfloat162*>(g_x_lo + i)[0] = __halves2bfloat162(l0, l1);
    reinterpret_cast<__nv_bfloat162*>(g_x_lo + i)[1] = __halves2bfloat162(l2, l3);
}

// ---------------- grouped GEMM (bf16x3, mma.sync, cp.async 2-stage) ----------------
__global__ void __launch_bounds__(256, 1) moe_gemm(
    const int* __restrict__ ssi, const int* __restrict__ eoff,
    const float* __restrict__ gates, float* __restrict__ out)
{
    extern __shared__ char smem[];
    uint32_t sb = (uint32_t)__cvta_generic_to_shared(smem);
    uint32_t aAhi[2] = { sb + 0u * TILEB, sb + 1u * TILEB };
    uint32_t aAlo[2] = { sb + 2u * TILEB, sb + 3u * TILEB };
    uint32_t aBhi[2] = { sb + 4u * TILEB, sb + 5u * TILEB };
    uint32_t aBlo[2] = { sb + 6u * TILEB, sb + 7u * TILEB };
    int*   tok_s  = reinterpret_cast<int*>(smem + 8 * TILEB);
    float* gate_s = reinterpret_cast<float*>(smem + 8 * TILEB + TM * 4);

    const int n0 = blockIdx.x * TN;   // n-tile fastest -> A tiles L2-resident across n
    const int mt = blockIdx.y;

    // map mt -> (expert, m0, mcnt) by scanning expert_offsets
    int expert = -1, m0 = 0, mcnt = 0;
    {
        int prev = 0, acc_t = 0;
        #pragma unroll
        for (int e = 0; e < EXP; e++) {
            int end = eoff[e];
            int cnt = end - prev;
            int tiles = (cnt + TM - 1) / TM;
            if (expert < 0 && mt >= acc_t && mt < acc_t + tiles) {
                expert = e;
                m0 = prev + (mt - acc_t) * TM;
                mcnt = end - m0;
                if (mcnt > TM) mcnt = TM;
            }
            acc_t += tiles;
            prev = end;
        }
    }
    if (expert < 0) return;

    const int tid  = threadIdx.x;
    const int lane = tid & 31;
    const int warp = tid >> 5;
    const int wm   = warp >> 1;   // 0..3 : 32-row slice
    const int wn   = warp & 1;    // 0..1 : 64-col slice

    if (tid < TM) {
        int tok = -1; float g = 0.f;
        if (tid < mcnt) {
            int s = ssi[m0 + tid];
            tok = s / KROUTE;
            int slot = s - tok * KROUTE;
            g = gates[tok * KROUTE + slot];
        }
        tok_s[tid]  = tok;
        gate_s[tid] = g;
    }
    __syncthreads();

    float acc[2][8][4];
    #pragma unroll
    for (int i = 0; i < 2; i++)
        #pragma unroll
        for (int j = 0; j < 8; j++)
            #pragma unroll
            for (int q = 0; q < 4; q++) acc[i][j][q] = 0.f;

    const size_t wbase = (size_t)expert * DOUT * DIN;

    auto load_stage = [&](int buf, int kb) {
        const int k0 = kb * TK;
        #pragma unroll
        for (int j = 0; j < 2; j++) {
            int idx = tid * 2 + j;        // 0..511
            int row = idx >> 2;           // 0..127
            int c   = idx & 3;            // 16B chunk within 64B row
            uint32_t soff = (uint32_t)(row * LDSS + c * 8) * 2;
            int tok = tok_s[row];
            size_t xoff = (size_t)(tok < 0 ? 0 : tok) * DIN + k0 + c * 8;
            int bytes = (tok < 0) ? 0 : 16;
            cpa16(aAhi[buf] + soff, g_x_hi + xoff, bytes);
            cpa16(aAlo[buf] + soff, g_x_lo + xoff, bytes);
            size_t woff = wbase + (size_t)(n0 + row) * DIN + k0 + c * 8;
            cpa16(aBhi[buf] + soff, g_w_hi + woff, 16);
            cpa16(aBlo[buf] + soff, g_w_lo + woff, 16);
        }
        cp_commit();
    };

    load_stage(0, 0);

    for (int kb = 0; kb < KB; kb++) {
        cp_wait0();
        __syncthreads();
        if (kb + 1 < KB) load_stage((kb + 1) & 1, kb + 1);
        const int buf = kb & 1;
        #pragma unroll
        for (int ks = 0; ks < 2; ks++) {
            uint32_t ah[2][4], al[2][4], bh[4][4], bl[4][4];
            int arow = wm * 32 + (lane & 15);
            int acol = ks * 16 + (lane >> 4) * 8;
            #pragma unroll
            for (int mi = 0; mi < 2; mi++) {
                uint32_t off = (uint32_t)((arow + mi * 16) * LDSS + acol) * 2;
                ldm4(ah[mi], aAhi[buf] + off);
                ldm4(al[mi], aAlo[buf] + off);
            }
            int brow = wn * 64 + (lane & 7) + ((lane >> 4) << 3);
            int bcol = ks * 16 + ((lane >> 3) & 1) * 8;
            #pragma unroll
            for (int nq = 0; nq < 4; nq++) {
                uint32_t off = (uint32_t)((brow + nq * 16) * LDSS + bcol) * 2;
                ldm4(bh[nq], aBhi[buf] + off);
                ldm4(bl[nq], aBlo[buf] + off);
            }
            #pragma unroll
            for (int ni = 0; ni < 8; ni++) {
                uint32_t b0h = bh[ni >> 1][(ni & 1) * 2 + 0];
                uint32_t b1h = bh[ni >> 1][(ni & 1) * 2 + 1];
                uint32_t b0l = bl[ni >> 1][(ni & 1) * 2 + 0];
                uint32_t b1l = bl[ni >> 1][(ni & 1) * 2 + 1];
                #pragma unroll
                for (int mi = 0; mi < 2; mi++) {
                    mma16816(acc[mi][ni], ah[mi], b0h, b1h);   // hi*hi
                    mma16816(acc[mi][ni], ah[mi], b0l, b1l);   // hi*lo
                    mma16816(acc[mi][ni], al[mi], b0h, b1h);   // lo*hi
                }
            }
        }
    }

    // epilogue: gate + scatter red.add (k=2 routes collide per token)
    const int g = lane >> 2, tg = lane & 3;
    #pragma unroll
    for (int mi = 0; mi < 2; mi++) {
        #pragma unroll
        for (int half = 0; half < 2; half++) {
            int mr = wm * 32 + mi * 16 + g + half * 8;
            int tok = tok_s[mr];
            if (tok < 0) continue;
            float gg = gate_s[mr];
            float* orow = out + (size_t)tok * DOUT + n0 + wn * 64 + tg * 2;
            #pragma unroll
            for (int ni = 0; ni < 8; ni++) {
                red2(orow + ni * 8,
                     acc[mi][ni][half * 2 + 0] * gg,
                     acc[mi][ni][half * 2 + 1] * gg);
            }
        }
    }
}

// ---------------- launch ----------------
extern "C" void kernel_launch(void* const* d_in, const int* in_sizes, int n_in,
                              void* d_out, int out_size) {
    const float* inputs = (const float*)d_in[0];
    const float* weight = (const float*)d_in[1];
    const float* lora_A = (const float*)d_in[2];
    const float* lora_B = (const float*)d_in[3];
    const float* gates  = (const float*)d_in[4];
    const int*   ssi    = (const int*)d_in[6];
    const int*   eoff   = (const int*)d_in[7];
    float* out = (float*)d_out;

    const int SMEM_BYTES = 8 * TILEB + TM * 8;   // 82944
    cudaFuncSetAttribute(moe_gemm, cudaFuncAttributeMaxDynamicSharedMemorySize, SMEM_BYTES);

    prep_weff_kernel<<<EXP * 32 * 32, 256>>>(weight, lora_A, lora_B);
    prep_x_kernel<<<(NTOK * DIN) / 1024, 256>>>(inputs);
    cudaMemsetAsync(d_out, 0, (size_t)out_size * sizeof(float));

    dim3 grid(DOUT / TN, MTOT / TM + EXP);   // 16 x 72 (max tiles incl. per-expert remainders)
    moe_gemm<<<grid, 256, SMEM_BYTES>>>(ssi, eoff, gates, out);
}

// round 3
// speedup vs baseline: 1.0354x; 1.0354x over previous
#include <cuda_runtime.h>
#include <cuda_bf16.h>
#include <cstdint>

#define EXP    8
#define DIN    2048
#define DOUT   2048
#define NTOK   4096
#define KROUTE 2
#define MTOT   (NTOK * KROUTE)

#define TM 128
#define TN 128
#define TK 32
#define KB (DIN / TK)             // 64
#define NSTG 3
#define LDSS 40                   // padded smem row stride in bf16 elems (80B)
#define TILEB (TM * LDSS * 2)     // 10240 bytes per tile
#define STGB  (4 * TILEB)         // Ahi,Alo,Bhi,Blo per stage

// ---- scratch (device globals; no runtime allocation allowed) ----
__device__ __nv_bfloat16 g_w_hi[(size_t)EXP * DOUT * DIN];
__device__ __nv_bfloat16 g_w_lo[(size_t)EXP * DOUT * DIN];
__device__ __nv_bfloat16 g_x_hi[(size_t)NTOK * DIN];
__device__ __nv_bfloat16 g_x_lo[(size_t)NTOK * DIN];

// ---------------- PTX helpers ----------------
__device__ __forceinline__ void cpa16(uint32_t dst, const void* src, int bytes) {
    asm volatile("cp.async.cg.shared.global [%0], [%1], 16, %2;\n"
                 :: "r"(dst), "l"(src), "r"(bytes));
}
__device__ __forceinline__ void cp_commit() { asm volatile("cp.async.commit_group;\n"); }

__device__ __forceinline__ void ldm4(uint32_t* r, uint32_t a) {
    asm volatile("ldmatrix.sync.aligned.m8n8.x4.shared.b16 {%0,%1,%2,%3}, [%4];\n"
                 : "=r"(r[0]), "=r"(r[1]), "=r"(r[2]), "=r"(r[3]) : "r"(a));
}
__device__ __forceinline__ void mma16816(float* c, const uint32_t* a, uint32_t b0, uint32_t b1) {
    asm volatile("mma.sync.aligned.m16n8k16.row.col.f32.bf16.bf16.f32 "
                 "{%0,%1,%2,%3}, {%4,%5,%6,%7}, {%8,%9}, {%0,%1,%2,%3};\n"
                 : "+f"(c[0]), "+f"(c[1]), "+f"(c[2]), "+f"(c[3])
                 : "r"(a[0]), "r"(a[1]), "r"(a[2]), "r"(a[3]), "r"(b0), "r"(b1));
}
__device__ __forceinline__ void red2(float* p, float v0, float v1) {
    asm volatile("red.global.add.v2.f32 [%0], {%1,%2};\n" :: "l"(p), "f"(v0), "f"(v1) : "memory");
}

// ---------------- prep: W_eff = W + 2*B@A, split to bf16 hi/lo ----------------
__global__ void __launch_bounds__(256) prep_weff_kernel(
    const float* __restrict__ weight, const float* __restrict__ lA,
    const float* __restrict__ lB)
{
    __shared__ float Bs[64][16];
    __shared__ float As[16][64];
    const int b = blockIdx.x;
    const int e = b >> 10;
    const int jt = (b >> 5) & 31;
    const int dt = b & 31;
    const int j0 = jt * 64, d0 = dt * 64;
    const int t = threadIdx.x;
    {
        int jj = t >> 2, q = t & 3;
        float4 v = *reinterpret_cast<const float4*>(lB + ((size_t)e * DOUT + j0 + jj) * 16 + q * 4);
        Bs[jj][q * 4 + 0] = v.x; Bs[jj][q * 4 + 1] = v.y;
        Bs[jj][q * 4 + 2] = v.z; Bs[jj][q * 4 + 3] = v.w;
    }
    {
        int r = t >> 4, dd = (t & 15) * 4;
        float4 v = *reinterpret_cast<const float4*>(lA + ((size_t)e * 16 + r) * DIN + d0 + dd);
        As[r][dd + 0] = v.x; As[r][dd + 1] = v.y; As[r][dd + 2] = v.z; As[r][dd + 3] = v.w;
    }
    __syncthreads();
    const int tj = t >> 4, td = t & 15;
    #pragma unroll
    for (int a = 0; a < 4; a++) {
        int jj = tj * 4 + a;
        size_t base = ((size_t)e * DOUT + j0 + jj) * DIN + d0 + td * 4;
        float4 w = *reinterpret_cast<const float4*>(weight + base);
        float dw0 = 0.f, dw1 = 0.f, dw2 = 0.f, dw3 = 0.f;
        #pragma unroll
        for (int r = 0; r < 16; r++) {
            float bb = Bs[jj][r];
            dw0 += bb * As[r][td * 4 + 0];
            dw1 += bb * As[r][td * 4 + 1];
            dw2 += bb * As[r][td * 4 + 2];
            dw3 += bb * As[r][td * 4 + 3];
        }
        float v0 = w.x + 2.0f * dw0;
        float v1 = w.y + 2.0f * dw1;
        float v2 = w.z + 2.0f * dw2;
        float v3 = w.w + 2.0f * dw3;
        __nv_bfloat16 h0 = __float2bfloat16(v0), h1 = __float2bfloat16(v1);
        __nv_bfloat16 h2 = __float2bfloat16(v2), h3 = __float2bfloat16(v3);
        reinterpret_cast<__nv_bfloat162*>(g_w_hi + base)[0] = __halves2bfloat162(h0, h1);
        reinterpret_cast<__nv_bfloat162*>(g_w_hi + base)[1] = __halves2bfloat162(h2, h3);
        __nv_bfloat16 L0 = __float2bfloat16(v0 - __bfloat162float(h0));
        __nv_bfloat16 L1 = __float2bfloat16(v1 - __bfloat162float(h1));
        __nv_bfloat16 L2 = __float2bfloat16(v2 - __bfloat162float(h2));
        __nv_bfloat16 L3 = __float2bfloat16(v3 - __bfloat162float(h3));
        reinterpret_cast<__nv_bfloat162*>(g_w_lo + base)[0] = __halves2bfloat162(L0, L1);
        reinterpret_cast<__nv_bfloat162*>(g_w_lo + base)[1] = __halves2bfloat162(L2, L3);
    }
}

// ---------------- prep: split inputs to bf16 hi/lo ----------------
__global__ void __launch_bounds__(256) prep_x_kernel(const float* __restrict__ x) {
    size_t i = ((size_t)blockIdx.x * 256 + threadIdx.x) * 4;
    float4 v = *reinterpret_cast<const float4*>(x + i);
    __nv_bfloat16 h0 = __float2bfloat16(v.x);
    __nv_bfloat16 h1 = __float2bfloat16(v.y);
    __nv_bfloat16 h2 = __float2bfloat16(v.z);
    __nv_bfloat16 h3 = __float2bfloat16(v.w);
    reinterpret_cast<__nv_bfloat162*>(g_x_hi + i)[0] = __halves2bfloat162(h0, h1);
    reinterpret_cast<__nv_bfloat162*>(g_x_hi + i)[1] = __halves2bfloat162(h2, h3);
    __nv_bfloat16 l0 = __float2bfloat16(v.x - __bfloat162float(h0));
    __nv_bfloat16 l1 = __float2bfloat16(v.y - __bfloat162float(h1));
    __nv_bfloat16 l2 = __float2bfloat16(v.z - __bfloat162float(h2));
    __nv_bfloat16 l3 = __float2bfloat16(v.w - __bfloat162float(h3));
    reinterpret_cast<__nv_bfloat162*>(g_x_lo + i)[0] = __halves2bfloat162(l0, l1);
    reinterpret_cast<__nv_bfloat162*>(g_x_lo + i)[1] = __halves2bfloat162(l2, l3);
}

// ---------------- grouped GEMM (bf16x3, mma.sync, cp.async 3-stage) ----------------
__global__ void __launch_bounds__(256, 1) moe_gemm(
    const int* __restrict__ ssi, const int* __restrict__ eoff,
    const float* __restrict__ gates, float* __restrict__ out)
{
    extern __shared__ __align__(256) char smem[];
    uint32_t sb = (uint32_t)__cvta_generic_to_shared(smem);
    int*   tok_s  = reinterpret_cast<int*>(smem);
    float* gate_s = reinterpret_cast<float*>(smem + TM * 4);
    const uint32_t sbuf = sb + 1024;

    const int n0 = blockIdx.x * TN;   // n fastest -> A tiles L2-resident across n
    const int mt = blockIdx.y;

    int expert = -1, m0 = 0, mcnt = 0;
    {
        int prev = 0, acc_t = 0;
        #pragma unroll
        for (int e = 0; e < EXP; e++) {
            int end = eoff[e];
            int cnt = end - prev;
            int tiles = (cnt + TM - 1) / TM;
            if (expert < 0 && mt >= acc_t && mt < acc_t + tiles) {
                expert = e;
                m0 = prev + (mt - acc_t) * TM;
                mcnt = end - m0;
                if (mcnt > TM) mcnt = TM;
            }
            acc_t += tiles;
            prev = end;
        }
    }
    if (expert < 0) return;

    const int tid  = threadIdx.x;
    const int lane = tid & 31;
    const int warp = tid >> 5;
    const int wm   = warp & 1;    // 0..1 : 64-row slice
    const int wn   = warp >> 1;   // 0..3 : 32-col slice

    if (tid < TM) {
        int tok = -1; float g = 0.f;
        if (tid < mcnt) {
            int s = ssi[m0 + tid];
            tok = s / KROUTE;
            int slot = s - tok * KROUTE;
            g = gates[tok * KROUTE + slot];
        }
        tok_s[tid]  = tok;
        gate_s[tid] = g;
    }
    __syncthreads();

    float acc[4][4][4];
    #pragma unroll
    for (int i = 0; i < 4; i++)
        #pragma unroll
        for (int j = 0; j < 4; j++)
            #pragma unroll
            for (int q = 0; q < 4; q++) acc[i][j][q] = 0.f;

    const size_t wbase = (size_t)expert * DOUT * DIN;

    auto load_stage = [&](int buf, int kb) {
        const int k0 = kb * TK;
        const uint32_t s = sbuf + (uint32_t)buf * STGB;
        #pragma unroll
        for (int j = 0; j < 2; j++) {
            int idx = tid * 2 + j;        // 0..511
            int row = idx >> 2;           // 0..127
            int c   = idx & 3;            // 16B chunk within 64B row
            uint32_t soff = (uint32_t)(row * LDSS + c * 8) * 2;
            int tok = tok_s[row];
            size_t xoff = (size_t)(tok < 0 ? 0 : tok) * DIN + k0 + c * 8;
            int bytes = (tok < 0) ? 0 : 16;
            cpa16(s + soff, g_x_hi + xoff, bytes);
            cpa16(s + TILEB + soff, g_x_lo + xoff, bytes);
            size_t woff = wbase + (size_t)(n0 + row) * DIN + k0 + c * 8;
            cpa16(s + 2 * TILEB + soff, g_w_hi + woff, 16);
            cpa16(s + 3 * TILEB + soff, g_w_lo + woff, 16);
        }
        cp_commit();
    };

    load_stage(0, 0);
    load_stage(1, 1);

    int buf = 0;
    for (int kb = 0; kb < KB; kb++) {
        asm volatile("cp.async.wait_group 1;\n");
        __syncthreads();
        if (kb + 2 < KB) load_stage((buf + 2 == NSTG) ? 0 : (buf + 2 - (buf + 2 >= NSTG ? NSTG : 0)), kb + 2);
        else cp_commit();   // keep group-count invariant for wait_group 1

        const uint32_t aHi = sbuf + (uint32_t)buf * STGB;
        const uint32_t aLo = aHi + TILEB;
        const uint32_t bHi = aHi + 2 * TILEB;
        const uint32_t bLo = aHi + 3 * TILEB;

        #pragma unroll
        for (int ks = 0; ks < 2; ks++) {
            uint32_t ah[4][4], al[4][4], bh[2][4], bl[2][4];
            int arow = wm * 64 + (lane & 15);
            int acol = ks * 16 + (lane >> 4) * 8;
            #pragma unroll
            for (int mi = 0; mi < 4; mi++) {
                uint32_t off = (uint32_t)((arow + mi * 16) * LDSS + acol) * 2;
                ldm4(ah[mi], aHi + off);
                ldm4(al[mi], aLo + off);
            }
            int brow = wn * 32 + (lane & 7) + ((lane >> 4) << 3);
            int bcol = ks * 16 + ((lane >> 3) & 1) * 8;
            #pragma unroll
            for (int nq = 0; nq < 2; nq++) {
                uint32_t off = (uint32_t)((brow + nq * 16) * LDSS + bcol) * 2;
                ldm4(bh[nq], bHi + off);
                ldm4(bl[nq], bLo + off);
            }
            #pragma unroll
            for (int ni = 0; ni < 4; ni++) {
                uint32_t b0h = bh[ni >> 1][(ni & 1) * 2 + 0];
                uint32_t b1h = bh[ni >> 1][(ni & 1) * 2 + 1];
                uint32_t b0l = bl[ni >> 1][(ni & 1) * 2 + 0];
                uint32_t b1l = bl[ni >> 1][(ni & 1) * 2 + 1];
                #pragma unroll
                for (int mi = 0; mi < 4; mi++) {
                    mma16816(acc[mi][ni], ah[mi], b0h, b1h);   // hi*hi
                    mma16816(acc[mi][ni], ah[mi], b0l, b1l);   // hi*lo
                    mma16816(acc[mi][ni], al[mi], b0h, b1h);   // lo*hi
                }
            }
        }
        buf = (buf + 1 == NSTG) ? 0 : buf + 1;
    }

    // epilogue: gate + scatter red.add (k=2 routes collide per token)
    const int g = lane >> 2, tg = lane & 3;
    #pragma unroll
    for (int mi = 0; mi < 4; mi++) {
        #pragma unroll
        for (int half = 0; half < 2; half++) {
            int mr = wm * 64 + mi * 16 + g + half * 8;
            int tok = tok_s[mr];
            if (tok < 0) continue;
            float gg = gate_s[mr];
            float* orow = out + (size_t)tok * DOUT + n0 + wn * 32 + tg * 2;
            #pragma unroll
            for (int ni = 0; ni < 4; ni++) {
                red2(orow + ni * 8,
                     acc[mi][ni][half * 2 + 0] * gg,
                     acc[mi][ni][half * 2 + 1] * gg);
            }
        }
    }
}

// ---------------- launch ----------------
extern "C" void kernel_launch(void* const* d_in, const int* in_sizes, int n_in,
                              void* d_out, int out_size) {
    const float* inputs = (const float*)d_in[0];
    const float* weight = (const float*)d_in[1];
    const float* lora_A = (const float*)d_in[2];
    const float* lora_B = (const float*)d_in[3];
    const float* gates  = (const float*)d_in[4];
    const int*   ssi    = (const int*)d_in[6];
    const int*   eoff   = (const int*)d_in[7];
    float* out = (float*)d_out;

    const int SMEM_BYTES = 1024 + NSTG * STGB;   // 1024 + 122880 = 123904
    cudaFuncSetAttribute(moe_gemm, cudaFuncAttributeMaxDynamicSharedMemorySize, SMEM_BYTES);

    prep_weff_kernel<<<EXP * 32 * 32, 256>>>(weight, lora_A, lora_B);
    prep_x_kernel<<<(NTOK * DIN) / 1024, 256>>>(inputs);
    cudaMemsetAsync(d_out, 0, (size_t)out_size * sizeof(float));

    dim3 grid(DOUT / TN, MTOT / TM + EXP);   // 16 x 72
    moe_gemm<<<grid, 256, SMEM_BYTES>>>(ssi, eoff, gates, out);
}

// round 4
// speedup vs baseline: 1.4945x; 1.4434x over previous
#include <cuda_runtime.h>
#include <cuda_fp16.h>
#include <cstdint>

#define EXP    8
#define DIN    2048
#define DOUT   2048
#define NTOK   4096
#define KROUTE 2
#define MTOT   (NTOK * KROUTE)

#define TM 128
#define TN 128
#define TK 32
#define KB (DIN / TK)             // 64
#define NSTG 4
#define LDSS 40                   // padded smem row stride in fp16 elems (80B)
#define TILEB (TM * LDSS * 2)     // 10240 bytes per tile
#define STGB  (3 * TILEB)         // Xhi, Xlo, W per stage

// ---- scratch (device globals; no runtime allocation allowed) ----
__device__ __half g_w  [(size_t)EXP * DOUT * DIN];
__device__ __half g_x_h[(size_t)NTOK * DIN];
__device__ __half g_x_l[(size_t)NTOK * DIN];

// ---------------- PTX helpers ----------------
__device__ __forceinline__ void cpa16(uint32_t dst, const void* src, int bytes) {
    asm volatile("cp.async.cg.shared.global [%0], [%1], 16, %2;\n"
                 :: "r"(dst), "l"(src), "r"(bytes));
}
__device__ __forceinline__ void cp_commit() { asm volatile("cp.async.commit_group;\n"); }

__device__ __forceinline__ void ldm4(uint32_t* r, uint32_t a) {
    asm volatile("ldmatrix.sync.aligned.m8n8.x4.shared.b16 {%0,%1,%2,%3}, [%4];\n"
                 : "=r"(r[0]), "=r"(r[1]), "=r"(r[2]), "=r"(r[3]) : "r"(a));
}
__device__ __forceinline__ void mma16816(float* c, const uint32_t* a, uint32_t b0, uint32_t b1) {
    asm volatile("mma.sync.aligned.m16n8k16.row.col.f32.f16.f16.f32 "
                 "{%0,%1,%2,%3}, {%4,%5,%6,%7}, {%8,%9}, {%0,%1,%2,%3};\n"
                 : "+f"(c[0]), "+f"(c[1]), "+f"(c[2]), "+f"(c[3])
                 : "r"(a[0]), "r"(a[1]), "r"(a[2]), "r"(a[3]), "r"(b0), "r"(b1));
}
__device__ __forceinline__ void red2(float* p, float v0, float v1) {
    asm volatile("red.global.add.v2.f32 [%0], {%1,%2};\n" :: "l"(p), "f"(v0), "f"(v1) : "memory");
}

// ---------------- prep: W_eff = W + 2*B@A, round to fp16 ----------------
__global__ void __launch_bounds__(256) prep_weff_kernel(
    const float* __restrict__ weight, const float* __restrict__ lA,
    const float* __restrict__ lB)
{
    __shared__ float Bs[64][16];
    __shared__ float As[16][64];
    const int b = blockIdx.x;
    const int e = b >> 10;
    const int jt = (b >> 5) & 31;
    const int dt = b & 31;
    const int j0 = jt * 64, d0 = dt * 64;
    const int t = threadIdx.x;
    {
        int jj = t >> 2, q = t & 3;
        float4 v = *reinterpret_cast<const float4*>(lB + ((size_t)e * DOUT + j0 + jj) * 16 + q * 4);
        Bs[jj][q * 4 + 0] = v.x; Bs[jj][q * 4 + 1] = v.y;
        Bs[jj][q * 4 + 2] = v.z; Bs[jj][q * 4 + 3] = v.w;
    }
    {
        int r = t >> 4, dd = (t & 15) * 4;
        float4 v = *reinterpret_cast<const float4*>(lA + ((size_t)e * 16 + r) * DIN + d0 + dd);
        As[r][dd + 0] = v.x; As[r][dd + 1] = v.y; As[r][dd + 2] = v.z; As[r][dd + 3] = v.w;
    }
    __syncthreads();
    const int tj = t >> 4, td = t & 15;
    #pragma unroll
    for (int a = 0; a < 4; a++) {
        int jj = tj * 4 + a;
        size_t base = ((size_t)e * DOUT + j0 + jj) * DIN + d0 + td * 4;
        float4 w = *reinterpret_cast<const float4*>(weight + base);
        float dw0 = 0.f, dw1 = 0.f, dw2 = 0.f, dw3 = 0.f;
        #pragma unroll
        for (int r = 0; r < 16; r++) {
            float bb = Bs[jj][r];
            dw0 += bb * As[r][td * 4 + 0];
            dw1 += bb * As[r][td * 4 + 1];
            dw2 += bb * As[r][td * 4 + 2];
            dw3 += bb * As[r][td * 4 + 3];
        }
        __half h0 = __float2half_rn(w.x + 2.0f * dw0);
        __half h1 = __float2half_rn(w.y + 2.0f * dw1);
        __half h2 = __float2half_rn(w.z + 2.0f * dw2);
        __half h3 = __float2half_rn(w.w + 2.0f * dw3);
        reinterpret_cast<__half2*>(g_w + base)[0] = __halves2half2(h0, h1);
        reinterpret_cast<__half2*>(g_w + base)[1] = __halves2half2(h2, h3);
    }
}

// ---------------- prep: split inputs to fp16 hi/lo ----------------
__global__ void __launch_bounds__(256) prep_x_kernel(const float* __restrict__ x) {
    size_t i = ((size_t)blockIdx.x * 256 + threadIdx.x) * 4;
    float4 v = *reinterpret_cast<const float4*>(x + i);
    __half h0 = __float2half_rn(v.x);
    __half h1 = __float2half_rn(v.y);
    __half h2 = __float2half_rn(v.z);
    __half h3 = __float2half_rn(v.w);
    reinterpret_cast<__half2*>(g_x_h + i)[0] = __halves2half2(h0, h1);
    reinterpret_cast<__half2*>(g_x_h + i)[1] = __halves2half2(h2, h3);
    __half l0 = __float2half_rn(v.x - __half2float(h0));
    __half l1 = __float2half_rn(v.y - __half2float(h1));
    __half l2 = __float2half_rn(v.z - __half2float(h2));
    __half l3 = __float2half_rn(v.w - __half2float(h3));
    reinterpret_cast<__half2*>(g_x_l + i)[0] = __halves2half2(l0, l1);
    reinterpret_cast<__half2*>(g_x_l + i)[1] = __halves2half2(l2, l3);
}

// ---------------- grouped GEMM (fp16x2, mma.sync, cp.async 4-stage, 512 thr) ----------------
__global__ void __launch_bounds__(512, 1) moe_gemm(
    const int* __restrict__ ssi, const int* __restrict__ eoff,
    const float* __restrict__ gates, float* __restrict__ out)
{
    extern __shared__ __align__(256) char smem[];
    uint32_t sb = (uint32_t)__cvta_generic_to_shared(smem);
    int*   tok_s  = reinterpret_cast<int*>(smem);
    float* gate_s = reinterpret_cast<float*>(smem + TM * 4);
    const uint32_t sbuf = sb + 1024;

    const int n0 = blockIdx.x * TN;   // n fastest -> A rows L2-resident across n
    const int mt = blockIdx.y;

    int expert = -1, m0 = 0, mcnt = 0;
    {
        int prev = 0, acc_t = 0;
        #pragma unroll
        for (int e = 0; e < EXP; e++) {
            int end = eoff[e];
            int cnt = end - prev;
            int tiles = (cnt + TM - 1) / TM;
            if (expert < 0 && mt >= acc_t && mt < acc_t + tiles) {
                expert = e;
                m0 = prev + (mt - acc_t) * TM;
                mcnt = end - m0;
                if (mcnt > TM) mcnt = TM;
            }
            acc_t += tiles;
            prev = end;
        }
    }
    if (expert < 0) return;

    const int tid  = threadIdx.x;
    const int lane = tid & 31;
    const int warp = tid >> 5;
    const int wm   = warp & 3;    // 0..3 : 32-row slice
    const int wn   = warp >> 2;   // 0..3 : 32-col slice

    if (tid < TM) {
        int tok = -1; float g = 0.f;
        if (tid < mcnt) {
            int s = ssi[m0 + tid];
            tok = s / KROUTE;
            int slot = s - tok * KROUTE;
            g = gates[tok * KROUTE + slot];
        }
        tok_s[tid]  = tok;
        gate_s[tid] = g;
    }
    __syncthreads();

    float acc[2][4][4];
    #pragma unroll
    for (int i = 0; i < 2; i++)
        #pragma unroll
        for (int j = 0; j < 4; j++)
            #pragma unroll
            for (int q = 0; q < 4; q++) acc[i][j][q] = 0.f;

    const size_t wbase = (size_t)expert * DOUT * DIN;

    auto load_stage = [&](int buf, int kb) {
        const int k0 = kb * TK;
        const uint32_t s = sbuf + (uint32_t)buf * STGB;
        int row = tid >> 2, c = tid & 3;          // 512 threads -> 1 chunk/tile each
        uint32_t soff = (uint32_t)(row * LDSS + c * 8) * 2;
        int tok = tok_s[row];
        size_t xoff = (size_t)(tok < 0 ? 0 : tok) * DIN + k0 + c * 8;
        int bytes = (tok < 0) ? 0 : 16;
        cpa16(s + soff, g_x_h + xoff, bytes);
        cpa16(s + TILEB + soff, g_x_l + xoff, bytes);
        size_t woff = wbase + (size_t)(n0 + row) * DIN + k0 + c * 8;
        cpa16(s + 2 * TILEB + soff, g_w + woff, 16);
        cp_commit();
    };

    load_stage(0, 0);
    load_stage(1, 1);
    load_stage(2, 2);

    int buf = 0;
    for (int kb = 0; kb < KB; kb++) {
        asm volatile("cp.async.wait_group 2;\n");
        __syncthreads();
        if (kb + 3 < KB) {
            int nb = buf + 3; if (nb >= NSTG) nb -= NSTG;
            load_stage(nb, kb + 3);
        } else {
            cp_commit();   // keep group-count invariant
        }

        const uint32_t aHi = sbuf + (uint32_t)buf * STGB;
        const uint32_t aLo = aHi + TILEB;
        const uint32_t bW  = aHi + 2 * TILEB;

        #pragma unroll
        for (int ks = 0; ks < 2; ks++) {
            uint32_t ah[2][4], al[2][4], bw[2][4];
            int arow = wm * 32 + (lane & 15);
            int acol = ks * 16 + (lane >> 4) * 8;
            #pragma unroll
            for (int mi = 0; mi < 2; mi++) {
                uint32_t off = (uint32_t)((arow + mi * 16) * LDSS + acol) * 2;
                ldm4(ah[mi], aHi + off);
                ldm4(al[mi], aLo + off);
            }
            int brow = wn * 32 + (lane & 7) + ((lane >> 4) << 3);
            int bcol = ks * 16 + ((lane >> 3) & 1) * 8;
            #pragma unroll
            for (int nq = 0; nq < 2; nq++) {
                uint32_t off = (uint32_t)((brow + nq * 16) * LDSS + bcol) * 2;
                ldm4(bw[nq], bW + off);
            }
            #pragma unroll
            for (int ni = 0; ni < 4; ni++) {
                uint32_t b0 = bw[ni >> 1][(ni & 1) * 2 + 0];
                uint32_t b1 = bw[ni >> 1][(ni & 1) * 2 + 1];
                #pragma unroll
                for (int mi = 0; mi < 2; mi++) {
                    mma16816(acc[mi][ni], ah[mi], b0, b1);   // xh * w
                    mma16816(acc[mi][ni], al[mi], b0, b1);   // xl * w
                }
            }
        }
        buf = (buf + 1 == NSTG) ? 0 : buf + 1;
    }

    // epilogue: gate + scatter red.add (k=2 routes collide per token)
    const int g = lane >> 2, tg = lane & 3;
    #pragma unroll
    for (int mi = 0; mi < 2; mi++) {
        #pragma unroll
        for (int half = 0; half < 2; half++) {
            int mr = wm * 32 + mi * 16 + g + half * 8;
            int tok = tok_s[mr];
            if (tok < 0) continue;
            float gg = gate_s[mr];
            float* orow = out + (size_t)tok * DOUT + n0 + wn * 32 + tg * 2;
            #pragma unroll
            for (int ni = 0; ni < 4; ni++) {
                red2(orow + ni * 8,
                     acc[mi][ni][half * 2 + 0] * gg,
                     acc[mi][ni][half * 2 + 1] * gg);
            }
        }
    }
}

// ---------------- launch ----------------
extern "C" void kernel_launch(void* const* d_in, const int* in_sizes, int n_in,
                              void* d_out, int out_size) {
    const float* inputs = (const float*)d_in[0];
    const float* weight = (const float*)d_in[1];
    const float* lora_A = (const float*)d_in[2];
    const float* lora_B = (const float*)d_in[3];
    const float* gates  = (const float*)d_in[4];
    const int*   ssi    = (const int*)d_in[6];
    const int*   eoff   = (const int*)d_in[7];
    float* out = (float*)d_out;

    const int SMEM_BYTES = 1024 + NSTG * STGB;   // 1024 + 122880 = 123904
    cudaFuncSetAttribute(moe_gemm, cudaFuncAttributeMaxDynamicSharedMemorySize, SMEM_BYTES);

    prep_weff_kernel<<<EXP * 32 * 32, 256>>>(weight, lora_A, lora_B);
    prep_x_kernel<<<(NTOK * DIN) / 1024, 256>>>(inputs);
    cudaMemsetAsync(d_out, 0, (size_t)out_size * sizeof(float));

    dim3 grid(DOUT / TN, MTOT / TM + EXP);   // 16 x 72
    moe_gemm<<<grid, 512, SMEM_BYTES>>>(ssi, eoff, gates, out);
}

// round 5
// speedup vs baseline: 2.2664x; 1.5166x over previous
#include <cuda_runtime.h>
#include <cuda_fp16.h>
#include <cstdint>

#define EXP    8
#define DIN    2048
#define DOUT   2048
#define NTOK   4096
#define KROUTE 2
#define MTOT   (NTOK * KROUTE)

#define TM 128
#define TN 128
#define TK 32
#define KB (DIN / TK)             // 64
#define NSTG 4
#define LDSS 40                   // padded smem row stride in fp16 elems (80B)
#define TILEB (TM * LDSS * 2)     // 10240 bytes per tile
#define STGB  (2 * TILEB)         // X, W per stage

// ---- scratch (device globals; no runtime allocation allowed) ----
__device__ __half g_w[(size_t)EXP * DOUT * DIN];
__device__ __half g_x[(size_t)NTOK * DIN];

// ---------------- PTX helpers ----------------
__device__ __forceinline__ void cpa16(uint32_t dst, const void* src, int bytes) {
    asm volatile("cp.async.cg.shared.global [%0], [%1], 16, %2;\n"
                 :: "r"(dst), "l"(src), "r"(bytes));
}
__device__ __forceinline__ void cp_commit() { asm volatile("cp.async.commit_group;\n"); }

__device__ __forceinline__ void ldm4(uint32_t* r, uint32_t a) {
    asm volatile("ldmatrix.sync.aligned.m8n8.x4.shared.b16 {%0,%1,%2,%3}, [%4];\n"
                 : "=r"(r[0]), "=r"(r[1]), "=r"(r[2]), "=r"(r[3]) : "r"(a));
}
__device__ __forceinline__ void mma16816(float* c, const uint32_t* a, uint32_t b0, uint32_t b1) {
    asm volatile("mma.sync.aligned.m16n8k16.row.col.f32.f16.f16.f32 "
                 "{%0,%1,%2,%3}, {%4,%5,%6,%7}, {%8,%9}, {%0,%1,%2,%3};\n"
                 : "+f"(c[0]), "+f"(c[1]), "+f"(c[2]), "+f"(c[3])
                 : "r"(a[0]), "r"(a[1]), "r"(a[2]), "r"(a[3]), "r"(b0), "r"(b1));
}
__device__ __forceinline__ void red2(float* p, float v0, float v1) {
    asm volatile("red.global.add.v2.f32 [%0], {%1,%2};\n" :: "l"(p), "f"(v0), "f"(v1) : "memory");
}

// ---------------- prep: W_eff = W + 2*B@A, round to fp16 ----------------
__global__ void __launch_bounds__(256) prep_weff_kernel(
    const float* __restrict__ weight, const float* __restrict__ lA,
    const float* __restrict__ lB)
{
    __shared__ float Bs[64][16];
    __shared__ float As[16][64];
    const int b = blockIdx.x;
    const int e = b >> 10;
    const int jt = (b >> 5) & 31;
    const int dt = b & 31;
    const int j0 = jt * 64, d0 = dt * 64;
    const int t = threadIdx.x;
    {
        int jj = t >> 2, q = t & 3;
        float4 v = *reinterpret_cast<const float4*>(lB + ((size_t)e * DOUT + j0 + jj) * 16 + q * 4);
        Bs[jj][q * 4 + 0] = v.x; Bs[jj][q * 4 + 1] = v.y;
        Bs[jj][q * 4 + 2] = v.z; Bs[jj][q * 4 + 3] = v.w;
    }
    {
        int r = t >> 4, dd = (t & 15) * 4;
        float4 v = *reinterpret_cast<const float4*>(lA + ((size_t)e * 16 + r) * DIN + d0 + dd);
        As[r][dd + 0] = v.x; As[r][dd + 1] = v.y; As[r][dd + 2] = v.z; As[r][dd + 3] = v.w;
    }
    __syncthreads();
    const int tj = t >> 4, td = t & 15;
    #pragma unroll
    for (int a = 0; a < 4; a++) {
        int jj = tj * 4 + a;
        size_t base = ((size_t)e * DOUT + j0 + jj) * DIN + d0 + td * 4;
        float4 w = *reinterpret_cast<const float4*>(weight + base);
        float dw0 = 0.f, dw1 = 0.f, dw2 = 0.f, dw3 = 0.f;
        #pragma unroll
        for (int r = 0; r < 16; r++) {
            float bb = Bs[jj][r];
            dw0 += bb * As[r][td * 4 + 0];
            dw1 += bb * As[r][td * 4 + 1];
            dw2 += bb * As[r][td * 4 + 2];
            dw3 += bb * As[r][td * 4 + 3];
        }
        __half h0 = __float2half_rn(w.x + 2.0f * dw0);
        __half h1 = __float2half_rn(w.y + 2.0f * dw1);
        __half h2 = __float2half_rn(w.z + 2.0f * dw2);
        __half h3 = __float2half_rn(w.w + 2.0f * dw3);
        reinterpret_cast<__half2*>(g_w + base)[0] = __halves2half2(h0, h1);
        reinterpret_cast<__half2*>(g_w + base)[1] = __halves2half2(h2, h3);
    }
}

// ---------------- prep: round inputs to fp16 ----------------
__global__ void __launch_bounds__(256) prep_x_kernel(const float* __restrict__ x) {
    size_t i = ((size_t)blockIdx.x * 256 + threadIdx.x) * 4;
    float4 v = *reinterpret_cast<const float4*>(x + i);
    reinterpret_cast<__half2*>(g_x + i)[0] =
        __halves2half2(__float2half_rn(v.x), __float2half_rn(v.y));
    reinterpret_cast<__half2*>(g_x + i)[1] =
        __halves2half2(__float2half_rn(v.z), __float2half_rn(v.w));
}

// ---------------- grouped GEMM (fp16, mma.sync, cp.async 4-stage, 512 thr) ----------------
__global__ void __launch_bounds__(512, 1) moe_gemm(
    const int* __restrict__ ssi, const int* __restrict__ eoff,
    const float* __restrict__ gates, float* __restrict__ out)
{
    extern __shared__ __align__(256) char smem[];
    uint32_t sb = (uint32_t)__cvta_generic_to_shared(smem);
    int*   tok_s  = reinterpret_cast<int*>(smem);
    float* gate_s = reinterpret_cast<float*>(smem + TM * 4);
    const uint32_t sbuf = sb + 1024;

    const int n0 = blockIdx.x * TN;   // n fastest -> x rows L2-resident across n
    const int mt = blockIdx.y;

    int expert = -1, m0 = 0, mcnt = 0;
    {
        int prev = 0, acc_t = 0;
        #pragma unroll
        for (int e = 0; e < EXP; e++) {
            int end = eoff[e];
            int cnt = end - prev;
            int tiles = (cnt + TM - 1) / TM;
            if (expert < 0 && mt >= acc_t && mt < acc_t + tiles) {
                expert = e;
                m0 = prev + (mt - acc_t) * TM;
                mcnt = end - m0;
                if (mcnt > TM) mcnt = TM;
            }
            acc_t += tiles;
            prev = end;
        }
    }
    if (expert < 0) return;

    const int tid  = threadIdx.x;
    const int lane = tid & 31;
    const int warp = tid >> 5;
    const int wm   = warp & 3;    // 0..3 : 32-row slice
    const int wn   = warp >> 2;   // 0..3 : 32-col slice

    if (tid < TM) {
        int tok = -1; float g = 0.f;
        if (tid < mcnt) {
            int s = ssi[m0 + tid];
            tok = s / KROUTE;
            int slot = s - tok * KROUTE;
            g = gates[tok * KROUTE + slot];
        }
        tok_s[tid]  = tok;
        gate_s[tid] = g;
    }
    __syncthreads();

    float acc[2][4][4];
    #pragma unroll
    for (int i = 0; i < 2; i++)
        #pragma unroll
        for (int j = 0; j < 4; j++)
            #pragma unroll
            for (int q = 0; q < 4; q++) acc[i][j][q] = 0.f;

    const size_t wbase = (size_t)expert * DOUT * DIN;

    auto load_stage = [&](int buf, int kb) {
        const int k0 = kb * TK;
        const uint32_t s = sbuf + (uint32_t)buf * STGB;
        int row = tid >> 2, c = tid & 3;          // 512 threads -> 1 chunk/tile each
        uint32_t soff = (uint32_t)(row * LDSS + c * 8) * 2;
        int tok = tok_s[row];
        size_t xoff = (size_t)(tok < 0 ? 0 : tok) * DIN + k0 + c * 8;
        int bytes = (tok < 0) ? 0 : 16;
        cpa16(s + soff, g_x + xoff, bytes);
        size_t woff = wbase + (size_t)(n0 + row) * DIN + k0 + c * 8;
        cpa16(s + TILEB + soff, g_w + woff, 16);
        cp_commit();
    };

    load_stage(0, 0);
    load_stage(1, 1);
    load_stage(2, 2);

    int buf = 0;
    for (int kb = 0; kb < KB; kb++) {
        asm volatile("cp.async.wait_group 2;\n");
        __syncthreads();
        if (kb + 3 < KB) {
            int nb = buf + 3; if (nb >= NSTG) nb -= NSTG;
            load_stage(nb, kb + 3);
        } else {
            cp_commit();   // keep group-count invariant
        }

        const uint32_t aX = sbuf + (uint32_t)buf * STGB;
        const uint32_t bW = aX + TILEB;

        #pragma unroll
        for (int ks = 0; ks < 2; ks++) {
            uint32_t ax[2][4], bw[2][4];
            int arow = wm * 32 + (lane & 15);
            int acol = ks * 16 + (lane >> 4) * 8;
            #pragma unroll
            for (int mi = 0; mi < 2; mi++) {
                uint32_t off = (uint32_t)((arow + mi * 16) * LDSS + acol) * 2;
                ldm4(ax[mi], aX + off);
            }
            int brow = wn * 32 + (lane & 7) + ((lane >> 4) << 3);
            int bcol = ks * 16 + ((lane >> 3) & 1) * 8;
            #pragma unroll
            for (int nq = 0; nq < 2; nq++) {
                uint32_t off = (uint32_t)((brow + nq * 16) * LDSS + bcol) * 2;
                ldm4(bw[nq], bW + off);
            }
            #pragma unroll
            for (int ni = 0; ni < 4; ni++) {
                uint32_t b0 = bw[ni >> 1][(ni & 1) * 2 + 0];
                uint32_t b1 = bw[ni >> 1][(ni & 1) * 2 + 1];
                #pragma unroll
                for (int mi = 0; mi < 2; mi++) {
                    mma16816(acc[mi][ni], ax[mi], b0, b1);
                }
            }
        }
        buf = (buf + 1 == NSTG) ? 0 : buf + 1;
    }

    // epilogue: gate + scatter red.add (k=2 routes collide per token)
    const int g = lane >> 2, tg = lane & 3;
    #pragma unroll
    for (int mi = 0; mi < 2; mi++) {
        #pragma unroll
        for (int half = 0; half < 2; half++) {
            int mr = wm * 32 + mi * 16 + g + half * 8;
            int tok = tok_s[mr];
            if (tok < 0) continue;
            float gg = gate_s[mr];
            float* orow = out + (size_t)tok * DOUT + n0 + wn * 32 + tg * 2;
            #pragma unroll
            for (int ni = 0; ni < 4; ni++) {
                red2(orow + ni * 8,
                     acc[mi][ni][half * 2 + 0] * gg,
                     acc[mi][ni][half * 2 + 1] * gg);
            }
        }
    }
}

// ---------------- launch ----------------
extern "C" void kernel_launch(void* const* d_in, const int* in_sizes, int n_in,
                              void* d_out, int out_size) {
    const float* inputs = (const float*)d_in[0];
    const float* weight = (const float*)d_in[1];
    const float* lora_A = (const float*)d_in[2];
    const float* lora_B = (const float*)d_in[3];
    const float* gates  = (const float*)d_in[4];
    const int*   ssi    = (const int*)d_in[6];
    const int*   eoff   = (const int*)d_in[7];
    float* out = (float*)d_out;

    const int SMEM_BYTES = 1024 + NSTG * STGB;   // 1024 + 81920 = 82944
    cudaFuncSetAttribute(moe_gemm, cudaFuncAttributeMaxDynamicSharedMemorySize, SMEM_BYTES);

    prep_weff_kernel<<<EXP * 32 * 32, 256>>>(weight, lora_A, lora_B);
    prep_x_kernel<<<(NTOK * DIN) / 1024, 256>>>(inputs);
    cudaMemsetAsync(d_out, 0, (size_t)out_size * sizeof(float));

    dim3 grid(DOUT / TN, MTOT / TM + EXP);   // 16 x 72
    moe_gemm<<<grid, 512, SMEM_BYTES>>>(ssi, eoff, gates, out);
}

// round 6
// speedup vs baseline: 2.5791x; 1.1379x over previous
#include <cuda_runtime.h>
#include <cuda_fp16.h>
#include <cstdint>

#define EXP    8
#define DIN    2048
#define DOUT   2048
#define NTOK   4096
#define KROUTE 2
#define MTOT   (NTOK * KROUTE)

#define TM 128
#define TN 128
#define TK 32
#define KB (DIN / TK)             // 64
#define NSTG 3
#define LDSS 40                   // padded smem row stride in fp16 elems (80B)
#define TILEB (TM * LDSS * 2)     // 10240 bytes per tile
#define STGB  (2 * TILEB)         // X, W per stage

// ---- scratch (device globals; no runtime allocation allowed) ----
__device__ __half g_w[(size_t)EXP * DOUT * DIN];
__device__ __half g_x[(size_t)NTOK * DIN];

// ---------------- PTX helpers ----------------
__device__ __forceinline__ void cpa16(uint32_t dst, const void* src, int bytes) {
    asm volatile("cp.async.cg.shared.global [%0], [%1], 16, %2;\n"
                 :: "r"(dst), "l"(src), "r"(bytes));
}
__device__ __forceinline__ void cp_commit() { asm volatile("cp.async.commit_group;\n"); }

__device__ __forceinline__ void ldm4(uint32_t* r, uint32_t a) {
    asm volatile("ldmatrix.sync.aligned.m8n8.x4.shared.b16 {%0,%1,%2,%3}, [%4];\n"
                 : "=r"(r[0]), "=r"(r[1]), "=r"(r[2]), "=r"(r[3]) : "r"(a));
}
__device__ __forceinline__ void mma16816(float* c, const uint32_t* a, uint32_t b0, uint32_t b1) {
    asm volatile("mma.sync.aligned.m16n8k16.row.col.f32.f16.f16.f32 "
                 "{%0,%1,%2,%3}, {%4,%5,%6,%7}, {%8,%9}, {%0,%1,%2,%3};\n"
                 : "+f"(c[0]), "+f"(c[1]), "+f"(c[2]), "+f"(c[3])
                 : "r"(a[0]), "r"(a[1]), "r"(a[2]), "r"(a[3]), "r"(b0), "r"(b1));
}
__device__ __forceinline__ void red2(float* p, float v0, float v1) {
    asm volatile("red.global.add.v2.f32 [%0], {%1,%2};\n" :: "l"(p), "f"(v0), "f"(v1) : "memory");
}

// ---------------- prep: W_eff = W + 2*B@A, round to fp16 ----------------
__global__ void __launch_bounds__(256) prep_weff_kernel(
    const float* __restrict__ weight, const float* __restrict__ lA,
    const float* __restrict__ lB)
{
    __shared__ float Bs[64][16];
    __shared__ float As[16][64];
    const int b = blockIdx.x;
    const int e = b >> 10;
    const int jt = (b >> 5) & 31;
    const int dt = b & 31;
    const int j0 = jt * 64, d0 = dt * 64;
    const int t = threadIdx.x;
    {
        int jj = t >> 2, q = t & 3;
        float4 v = *reinterpret_cast<const float4*>(lB + ((size_t)e * DOUT + j0 + jj) * 16 + q * 4);
        Bs[jj][q * 4 + 0] = v.x; Bs[jj][q * 4 + 1] = v.y;
        Bs[jj][q * 4 + 2] = v.z; Bs[jj][q * 4 + 3] = v.w;
    }
    {
        int r = t >> 4, dd = (t & 15) * 4;
        float4 v = *reinterpret_cast<const float4*>(lA + ((size_t)e * 16 + r) * DIN + d0 + dd);
        As[r][dd + 0] = v.x; As[r][dd + 1] = v.y; As[r][dd + 2] = v.z; As[r][dd + 3] = v.w;
    }
    __syncthreads();
    const int tj = t >> 4, td = t & 15;
    #pragma unroll
    for (int a = 0; a < 4; a++) {
        int jj = tj * 4 + a;
        size_t base = ((size_t)e * DOUT + j0 + jj) * DIN + d0 + td * 4;
        float4 w = *reinterpret_cast<const float4*>(weight + base);
        float dw0 = 0.f, dw1 = 0.f, dw2 = 0.f, dw3 = 0.f;
        #pragma unroll
        for (int r = 0; r < 16; r++) {
            float bb = Bs[jj][r];
            dw0 += bb * As[r][td * 4 + 0];
            dw1 += bb * As[r][td * 4 + 1];
            dw2 += bb * As[r][td * 4 + 2];
            dw3 += bb * As[r][td * 4 + 3];
        }
        __half h0 = __float2half_rn(w.x + 2.0f * dw0);
        __half h1 = __float2half_rn(w.y + 2.0f * dw1);
        __half h2 = __float2half_rn(w.z + 2.0f * dw2);
        __half h3 = __float2half_rn(w.w + 2.0f * dw3);
        reinterpret_cast<__half2*>(g_w + base)[0] = __halves2half2(h0, h1);
        reinterpret_cast<__half2*>(g_w + base)[1] = __halves2half2(h2, h3);
    }
}

// ---------------- prep: round inputs to fp16 ----------------
__global__ void __launch_bounds__(256) prep_x_kernel(const float* __restrict__ x) {
    size_t i = ((size_t)blockIdx.x * 256 + threadIdx.x) * 4;
    float4 v = *reinterpret_cast<const float4*>(x + i);
    reinterpret_cast<__half2*>(g_x + i)[0] =
        __halves2half2(__float2half_rn(v.x), __float2half_rn(v.y));
    reinterpret_cast<__half2*>(g_x + i)[1] =
        __halves2half2(__float2half_rn(v.z), __float2half_rn(v.w));
}

// ---------------- grouped GEMM (fp16, mma.sync, 3-stage, 512 thr, 2 CTA/SM) ----------------
__global__ void __launch_bounds__(512, 2) moe_gemm(
    const int* __restrict__ ssi, const int* __restrict__ eoff,
    const float* __restrict__ gates, float* __restrict__ out)
{
    extern __shared__ __align__(256) char smem[];
    uint32_t sb = (uint32_t)__cvta_generic_to_shared(smem);
    int*   tok_s  = reinterpret_cast<int*>(smem);
    float* gate_s = reinterpret_cast<float*>(smem + TM * 4);
    const uint32_t sbuf = sb + 1024;

    const int n0 = blockIdx.x * TN;   // n fastest -> x rows L2-resident across n
    const int mt = blockIdx.y;

    int expert = -1, m0 = 0, mcnt = 0;
    {
        int prev = 0, acc_t = 0;
        #pragma unroll
        for (int e = 0; e < EXP; e++) {
            int end = eoff[e];
            int cnt = end - prev;
            int tiles = (cnt + TM - 1) / TM;
            if (expert < 0 && mt >= acc_t && mt < acc_t + tiles) {
                expert = e;
                m0 = prev + (mt - acc_t) * TM;
                mcnt = end - m0;
                if (mcnt > TM) mcnt = TM;
            }
            acc_t += tiles;
            prev = end;
        }
    }
    if (expert < 0) return;

    const int tid  = threadIdx.x;
    const int lane = tid & 31;
    const int warp = tid >> 5;
    const int wm   = warp & 3;    // 0..3 : 32-row slice
    const int wn   = warp >> 2;   // 0..3 : 32-col slice

    if (tid < TM) {
        int tok = -1; float g = 0.f;
        if (tid < mcnt) {
            int s = ssi[m0 + tid];
            tok = s / KROUTE;
            int slot = s - tok * KROUTE;
            g = gates[tok * KROUTE + slot];
        }
        tok_s[tid]  = tok;
        gate_s[tid] = g;
    }
    __syncthreads();

    float acc[2][4][4];
    #pragma unroll
    for (int i = 0; i < 2; i++)
        #pragma unroll
        for (int j = 0; j < 4; j++)
            #pragma unroll
            for (int q = 0; q < 4; q++) acc[i][j][q] = 0.f;

    const size_t wbase = (size_t)expert * DOUT * DIN;

    auto load_stage = [&](int buf, int kb) {
        const int k0 = kb * TK;
        const uint32_t s = sbuf + (uint32_t)buf * STGB;
        int row = tid >> 2, c = tid & 3;          // 512 threads -> 1 chunk/tile each
        uint32_t soff = (uint32_t)(row * LDSS + c * 8) * 2;
        int tok = tok_s[row];
        size_t xoff = (size_t)(tok < 0 ? 0 : tok) * DIN + k0 + c * 8;
        int bytes = (tok < 0) ? 0 : 16;
        cpa16(s + soff, g_x + xoff, bytes);
        size_t woff = wbase + (size_t)(n0 + row) * DIN + k0 + c * 8;
        cpa16(s + TILEB + soff, g_w + woff, 16);
        cp_commit();
    };

    load_stage(0, 0);
    load_stage(1, 1);

    int buf = 0;
    for (int kb = 0; kb < KB; kb++) {
        asm volatile("cp.async.wait_group 1;\n");
        __syncthreads();
        if (kb + 2 < KB) {
            int nb = buf + 2; if (nb >= NSTG) nb -= NSTG;
            load_stage(nb, kb + 2);
        } else {
            cp_commit();   // keep group-count invariant
        }

        const uint32_t aX = sbuf + (uint32_t)buf * STGB;
        const uint32_t bW = aX + TILEB;

        #pragma unroll
        for (int ks = 0; ks < 2; ks++) {
            uint32_t ax[2][4], bw[2][4];
            int arow = wm * 32 + (lane & 15);
            int acol = ks * 16 + (lane >> 4) * 8;
            #pragma unroll
            for (int mi = 0; mi < 2; mi++) {
                uint32_t off = (uint32_t)((arow + mi * 16) * LDSS + acol) * 2;
                ldm4(ax[mi], aX + off);
            }
            int brow = wn * 32 + (lane & 7) + ((lane >> 4) << 3);
            int bcol = ks * 16 + ((lane >> 3) & 1) * 8;
            #pragma unroll
            for (int nq = 0; nq < 2; nq++) {
                uint32_t off = (uint32_t)((brow + nq * 16) * LDSS + bcol) * 2;
                ldm4(bw[nq], bW + off);
            }
            #pragma unroll
            for (int ni = 0; ni < 4; ni++) {
                uint32_t b0 = bw[ni >> 1][(ni & 1) * 2 + 0];
                uint32_t b1 = bw[ni >> 1][(ni & 1) * 2 + 1];
                #pragma unroll
                for (int mi = 0; mi < 2; mi++) {
                    mma16816(acc[mi][ni], ax[mi], b0, b1);
                }
            }
        }
        buf = (buf + 1 == NSTG) ? 0 : buf + 1;
    }

    // epilogue: gate + scatter red.add (k=2 routes collide per token)
    const int g = lane >> 2, tg = lane & 3;
    #pragma unroll
    for (int mi = 0; mi < 2; mi++) {
        #pragma unroll
        for (int half = 0; half < 2; half++) {
            int mr = wm * 32 + mi * 16 + g + half * 8;
            int tok = tok_s[mr];
            if (tok < 0) continue;
            float gg = gate_s[mr];
            float* orow = out + (size_t)tok * DOUT + n0 + wn * 32 + tg * 2;
            #pragma unroll
            for (int ni = 0; ni < 4; ni++) {
                red2(orow + ni * 8,
                     acc[mi][ni][half * 2 + 0] * gg,
                     acc[mi][ni][half * 2 + 1] * gg);
            }
        }
    }
}

// ---------------- launch ----------------
extern "C" void kernel_launch(void* const* d_in, const int* in_sizes, int n_in,
                              void* d_out, int out_size) {
    const float* inputs = (const float*)d_in[0];
    const float* weight = (const float*)d_in[1];
    const float* lora_A = (const float*)d_in[2];
    const float* lora_B = (const float*)d_in[3];
    const float* gates  = (const float*)d_in[4];
    const int*   ssi    = (const int*)d_in[6];
    const int*   eoff   = (const int*)d_in[7];
    float* out = (float*)d_out;

    const int SMEM_BYTES = 1024 + NSTG * STGB;   // 1024 + 61440 = 62464
    cudaFuncSetAttribute(moe_gemm, cudaFuncAttributeMaxDynamicSharedMemorySize, SMEM_BYTES);

    prep_weff_kernel<<<EXP * 32 * 32, 256>>>(weight, lora_A, lora_B);
    prep_x_kernel<<<(NTOK * DIN) / 1024, 256>>>(inputs);
    cudaMemsetAsync(d_out, 0, (size_t)out_size * sizeof(float));

    dim3 grid(DOUT / TN, MTOT / TM + EXP);   // 16 x 72
    moe_gemm<<<grid, 512, SMEM_BYTES>>>(ssi, eoff, gates, out);
}

// round 7
// speedup vs baseline: 2.6905x; 1.0432x over previous
#include <cuda_runtime.h>
#include <cuda_fp16.h>
#include <cstdint>

#define EXP    8
#define DIN    2048
#define DOUT   2048
#define NTOK   4096
#define KROUTE 2
#define MTOT   (NTOK * KROUTE)

#define TM 128
#define TN 128
#define TK 64
#define KB (DIN / TK)             // 32
#define NSTG 3
#define LDSS 72                   // padded smem row stride in fp16 elems (144B)
#define TILEB (TM * LDSS * 2)     // 18432 bytes per tile
#define STGB  (2 * TILEB)         // X, W per stage = 36864

// ---- scratch (device globals; no runtime allocation allowed) ----
__device__ __half g_w[(size_t)EXP * DOUT * DIN];
__device__ __half g_x[(size_t)NTOK * DIN];

// ---------------- PTX helpers ----------------
__device__ __forceinline__ void cpa16(uint32_t dst, const void* src, int bytes) {
    asm volatile("cp.async.cg.shared.global [%0], [%1], 16, %2;\n"
                 :: "r"(dst), "l"(src), "r"(bytes));
}
__device__ __forceinline__ void cp_commit() { asm volatile("cp.async.commit_group;\n"); }

__device__ __forceinline__ void ldm4(uint32_t* r, uint32_t a) {
    asm volatile("ldmatrix.sync.aligned.m8n8.x4.shared.b16 {%0,%1,%2,%3}, [%4];\n"
                 : "=r"(r[0]), "=r"(r[1]), "=r"(r[2]), "=r"(r[3]) : "r"(a));
}
__device__ __forceinline__ void mma16816(float* c, const uint32_t* a, uint32_t b0, uint32_t b1) {
    asm volatile("mma.sync.aligned.m16n8k16.row.col.f32.f16.f16.f32 "
                 "{%0,%1,%2,%3}, {%4,%5,%6,%7}, {%8,%9}, {%0,%1,%2,%3};\n"
                 : "+f"(c[0]), "+f"(c[1]), "+f"(c[2]), "+f"(c[3])
                 : "r"(a[0]), "r"(a[1]), "r"(a[2]), "r"(a[3]), "r"(b0), "r"(b1));
}
__device__ __forceinline__ void red2(float* p, float v0, float v1) {
    asm volatile("red.global.add.v2.f32 [%0], {%1,%2};\n" :: "l"(p), "f"(v0), "f"(v1) : "memory");
}

// ---------------- prep: W_eff = W + 2*B@A, round to fp16 ----------------
// thread t: j-row = t>>2, d-cols = (t&3)*4 + i*16, i=0..3 (4 chunks of 4)
__global__ void __launch_bounds__(256) prep_weff_kernel(
    const float* __restrict__ weight, const float* __restrict__ lA,
    const float* __restrict__ lB)
{
    __shared__ float Bs[64][17];
    __shared__ float As[16][68];
    const int b = blockIdx.x;
    const int e = b >> 10;
    const int jt = (b >> 5) & 31;
    const int dt = b & 31;
    const int j0 = jt * 64, d0 = dt * 64;
    const int t = threadIdx.x;
    {
        int jj = t >> 2, q = t & 3;
        float4 v = *reinterpret_cast<const float4*>(lB + ((size_t)e * DOUT + j0 + jj) * 16 + q * 4);
        Bs[jj][q * 4 + 0] = v.x; Bs[jj][q * 4 + 1] = v.y;
        Bs[jj][q * 4 + 2] = v.z; Bs[jj][q * 4 + 3] = v.w;
    }
    {
        int r = t >> 4, dd = (t & 15) * 4;
        float4 v = *reinterpret_cast<const float4*>(lA + ((size_t)e * 16 + r) * DIN + d0 + dd);
        As[r][dd + 0] = v.x; As[r][dd + 1] = v.y; As[r][dd + 2] = v.z; As[r][dd + 3] = v.w;
    }
    __syncthreads();

    const int j = t >> 2;
    const int q = t & 3;
    const size_t base = ((size_t)e * DOUT + j0 + j) * DIN + d0 + q * 4;

    float acc[4][4];
    #pragma unroll
    for (int i = 0; i < 4; i++) {
        float4 w = *reinterpret_cast<const float4*>(weight + base + i * 16);
        acc[i][0] = w.x; acc[i][1] = w.y; acc[i][2] = w.z; acc[i][3] = w.w;
    }
    #pragma unroll
    for (int r = 0; r < 16; r++) {
        float bb = 2.0f * Bs[j][r];
        #pragma unroll
        for (int i = 0; i < 4; i++) {
            const float* a4 = &As[r][q * 4 + i * 16];
            acc[i][0] += bb * a4[0];
            acc[i][1] += bb * a4[1];
            acc[i][2] += bb * a4[2];
            acc[i][3] += bb * a4[3];
        }
    }
    #pragma unroll
    for (int i = 0; i < 4; i++) {
        __half2 h0 = __halves2half2(__float2half_rn(acc[i][0]), __float2half_rn(acc[i][1]));
        __half2 h1 = __halves2half2(__float2half_rn(acc[i][2]), __float2half_rn(acc[i][3]));
        uint2 pk;
        pk.x = *reinterpret_cast<uint32_t*>(&h0);
        pk.y = *reinterpret_cast<uint32_t*>(&h1);
        *reinterpret_cast<uint2*>(g_w + base + i * 16) = pk;
    }
}

// ---------------- prep: round inputs to fp16 ----------------
__global__ void __launch_bounds__(256) prep_x_kernel(const float* __restrict__ x) {
    size_t i = ((size_t)blockIdx.x * 256 + threadIdx.x) * 4;
    float4 v = *reinterpret_cast<const float4*>(x + i);
    reinterpret_cast<__half2*>(g_x + i)[0] =
        __halves2half2(__float2half_rn(v.x), __float2half_rn(v.y));
    reinterpret_cast<__half2*>(g_x + i)[1] =
        __halves2half2(__float2half_rn(v.z), __float2half_rn(v.w));
}

// ---------------- grouped GEMM (fp16, mma.sync, TK=64, 3-stage, 512 thr, 2 CTA/SM) ----------------
__global__ void __launch_bounds__(512, 2) moe_gemm(
    const int* __restrict__ ssi, const int* __restrict__ eoff,
    const float* __restrict__ gates, float* __restrict__ out)
{
    extern __shared__ __align__(256) char smem[];
    uint32_t sb = (uint32_t)__cvta_generic_to_shared(smem);
    int*   tok_s  = reinterpret_cast<int*>(smem);
    float* gate_s = reinterpret_cast<float*>(smem + TM * 4);
    const uint32_t sbuf = sb + 1024;

    const int n0 = blockIdx.x * TN;   // n fastest -> x rows L2-resident across n
    const int mt = blockIdx.y;

    int expert = -1, m0 = 0, mcnt = 0;
    {
        int prev = 0, acc_t = 0;
        #pragma unroll
        for (int e = 0; e < EXP; e++) {
            int end = eoff[e];
            int cnt = end - prev;
            int tiles = (cnt + TM - 1) / TM;
            if (expert < 0 && mt >= acc_t && mt < acc_t + tiles) {
                expert = e;
                m0 = prev + (mt - acc_t) * TM;
                mcnt = end - m0;
                if (mcnt > TM) mcnt = TM;
            }
            acc_t += tiles;
            prev = end;
        }
    }
    if (expert < 0) return;

    const int tid  = threadIdx.x;
    const int lane = tid & 31;
    const int warp = tid >> 5;
    const int wm   = warp & 3;    // 0..3 : 32-row slice
    const int wn   = warp >> 2;   // 0..3 : 32-col slice

    if (tid < TM) {
        int tok = -1; float g = 0.f;
        if (tid < mcnt) {
            int s = ssi[m0 + tid];
            tok = s / KROUTE;
            int slot = s - tok * KROUTE;
            g = gates[tok * KROUTE + slot];
        }
        tok_s[tid]  = tok;
        gate_s[tid] = g;
    }
    __syncthreads();

    float acc[2][4][4];
    #pragma unroll
    for (int i = 0; i < 2; i++)
        #pragma unroll
        for (int j = 0; j < 4; j++)
            #pragma unroll
            for (int q = 0; q < 4; q++) acc[i][j][q] = 0.f;

    const size_t wbase = (size_t)expert * DOUT * DIN;

    auto load_stage = [&](int buf, int kb) {
        const int k0 = kb * TK;
        const uint32_t s = sbuf + (uint32_t)buf * STGB;
        #pragma unroll
        for (int it = 0; it < 2; it++) {
            int idx = tid + it * 512;         // 0..1023
            int row = idx >> 3, c = idx & 7;  // 8 chunks of 16B per 128B row
            uint32_t soff = (uint32_t)(row * (LDSS * 2) + c * 16);
            int tok = tok_s[row];
            size_t xoff = (size_t)(tok < 0 ? 0 : tok) * DIN + k0 + c * 8;
            int bytes = (tok < 0) ? 0 : 16;
            cpa16(s + soff, g_x + xoff, bytes);
            size_t woff = wbase + (size_t)(n0 + row) * DIN + k0 + c * 8;
            cpa16(s + TILEB + soff, g_w + woff, 16);
        }
        cp_commit();
    };

    load_stage(0, 0);
    load_stage(1, 1);

    int buf = 0;
    for (int kb = 0; kb < KB; kb++) {
        asm volatile("cp.async.wait_group 1;\n");
        __syncthreads();
        if (kb + 2 < KB) {
            int nb = buf + 2; if (nb >= NSTG) nb -= NSTG;
            load_stage(nb, kb + 2);
        } else {
            cp_commit();   // keep group-count invariant
        }

        const uint32_t aX = sbuf + (uint32_t)buf * STGB;
        const uint32_t bW = aX + TILEB;

        #pragma unroll
        for (int ks = 0; ks < 4; ks++) {
            uint32_t ax[2][4], bw[2][4];
            int arow = wm * 32 + (lane & 15);
            int acol = ks * 16 + (lane >> 4) * 8;
            #pragma unroll
            for (int mi = 0; mi < 2; mi++) {
                uint32_t off = (uint32_t)((arow + mi * 16) * LDSS + acol) * 2;
                ldm4(ax[mi], aX + off);
            }
            int brow = wn * 32 + (lane & 7) + ((lane >> 4) << 3);
            int bcol = ks * 16 + ((lane >> 3) & 1) * 8;
            #pragma unroll
            for (int nq = 0; nq < 2; nq++) {
                uint32_t off = (uint32_t)((brow + nq * 16) * LDSS + bcol) * 2;
                ldm4(bw[nq], bW + off);
            }
            #pragma unroll
            for (int ni = 0; ni < 4; ni++) {
                uint32_t b0 = bw[ni >> 1][(ni & 1) * 2 + 0];
                uint32_t b1 = bw[ni >> 1][(ni & 1) * 2 + 1];
                #pragma unroll
                for (int mi = 0; mi < 2; mi++) {
                    mma16816(acc[mi][ni], ax[mi], b0, b1);
                }
            }
        }
        buf = (buf + 1 == NSTG) ? 0 : buf + 1;
    }

    // epilogue: gate + scatter red.add (k=2 routes collide per token)
    const int g = lane >> 2, tg = lane & 3;
    #pragma unroll
    for (int mi = 0; mi < 2; mi++) {
        #pragma unroll
        for (int half = 0; half < 2; half++) {
            int mr = wm * 32 + mi * 16 + g + half * 8;
            int tok = tok_s[mr];
            if (tok < 0) continue;
            float gg = gate_s[mr];
            float* orow = out + (size_t)tok * DOUT + n0 + wn * 32 + tg * 2;
            #pragma unroll
            for (int ni = 0; ni < 4; ni++) {
                red2(orow + ni * 8,
                     acc[mi][ni][half * 2 + 0] * gg,
                     acc[mi][ni][half * 2 + 1] * gg);
            }
        }
    }
}

// ---------------- launch ----------------
extern "C" void kernel_launch(void* const* d_in, const int* in_sizes, int n_in,
                              void* d_out, int out_size) {
    const float* inputs = (const float*)d_in[0];
    const float* weight = (const float*)d_in[1];
    const float* lora_A = (const float*)d_in[2];
    const float* lora_B = (const float*)d_in[3];
    const float* gates  = (const float*)d_in[4];
    const int*   ssi    = (const int*)d_in[6];
    const int*   eoff   = (const int*)d_in[7];
    float* out = (float*)d_out;

    const int SMEM_BYTES = 1024 + NSTG * STGB;   // 1024 + 110592 = 111616
    cudaFuncSetAttribute(moe_gemm, cudaFuncAttributeMaxDynamicSharedMemorySize, SMEM_BYTES);

    prep_weff_kernel<<<EXP * 32 * 32, 256>>>(weight, lora_A, lora_B);
    prep_x_kernel<<<(NTOK * DIN) / 1024, 256>>>(inputs);
    cudaMemsetAsync(d_out, 0, (size_t)out_size * sizeof(float));

    dim3 grid(DOUT / TN, MTOT / TM + EXP);   // 16 x 72
    moe_gemm<<<grid, 512, SMEM_BYTES>>>(ssi, eoff, gates, out);
}